// round 2
// baseline (speedup 1.0000x reference)
#include <cuda_runtime.h>

#define NQ       22
#define DIM      (1u << NQ)        // 4194304
#define BLOG     13
#define CHUNK    (1u << BLOG)      // 8192 elements per CTA (in smem)
#define NTHREADS 512
#define GROUPS   (CHUNK >> 2)      // 2048 float4 groups per chunk
#define GPT      (GROUPS / NTHREADS) // 4 float4 groups per thread
#define NBLOCKS  (DIM / CHUNK)     // 512
#define SMEM_BYTES (2 * GROUPS * 16) // 64 KB

// Scratch (device globals, no allocation)
__device__ float g_diag[DIM];
__device__ float g_dLo[2048];
__device__ float g_dHi[2048];
__device__ float g_R[11][2048];

// ---------------------------------------------------------------------------
// Kernel A: tiny split tables for the diagonal.
//   LSB bit positions p>q carry coefficient M[p][q] = U[21-p][21-q]
//   dLo[lo]  : one-body + pairwise among bits 0..10
//   dHi[hi]  : one-body + pairwise among bits 11..21 (hi bit h -> global 11+h)
//   R[h][lo] : cross terms, sum over set q in lo of U[10-h][21-q]
// ---------------------------------------------------------------------------
__global__ void tables_kernel(const float* __restrict__ U,
                              const float* __restrict__ detune)
{
    int t = blockIdx.x * blockDim.x + threadIdx.x;
    if (t >= 2048) return;
    float det = detune[0];

    float dlo = 0.f;
    for (int p = 0; p < 11; p++) {
        if ((t >> p) & 1) {
            dlo -= det;
            for (int q = 0; q < p; q++)
                if ((t >> q) & 1) dlo += U[(21 - p) * NQ + (21 - q)];
        }
    }
    g_dLo[t] = dlo;

    float dhi = 0.f;
    for (int h = 0; h < 11; h++) {
        if ((t >> h) & 1) {
            dhi -= det;
            for (int h2 = 0; h2 < h; h2++)
                if ((t >> h2) & 1) dhi += U[(10 - h) * NQ + (10 - h2)];
        }
    }
    g_dHi[t] = dhi;

    for (int h = 0; h < 11; h++) {
        float r = 0.f;
        for (int q = 0; q < 11; q++)
            if ((t >> q) & 1) r += U[(10 - h) * NQ + (21 - q)];
        g_R[h][t] = r;
    }
}

// ---------------------------------------------------------------------------
// Kernel B: fill full diagonal array (4M floats) from the split tables.
//   diag[b] = dLo[b & 2047] + dHi[b >> 11] + sum_{h set in hi} R[h][b & 2047]
// Vectorized float4 over lo (tables L1/L2 resident). Branches warp-uniform.
// ---------------------------------------------------------------------------
__global__ void diag_kernel()
{
    unsigned g  = blockIdx.x * blockDim.x + threadIdx.x;  // float4 group id
    unsigned b  = g << 2;
    unsigned lo = b & 2047u;
    unsigned hi = b >> 11;

    float4 d = *(const float4*)&g_dLo[lo];
    float dhi = g_dHi[hi];
    d.x += dhi; d.y += dhi; d.z += dhi; d.w += dhi;
#pragma unroll
    for (int h = 0; h < 11; h++) {
        if ((hi >> h) & 1) {
            float4 r = *(const float4*)&g_R[h][lo];
            d.x += r.x; d.y += r.y; d.z += r.z; d.w += r.w;
        }
    }
    ((float4*)g_diag)[g] = d;
}

// ---------------------------------------------------------------------------
// Kernel C: main apply.
//   out = (rabi/2) * sum over 22 single-bit-flip neighbors + diag * psi
//   bits 0..1   : inside the float4 (register swaps)
//   bits 2..12  : group-XOR inside the 8K-element smem tile (LDS.128)
//   bits 13..21 : coalesced global float4 loads of 9 neighbor chunks
// ---------------------------------------------------------------------------
__global__ void __launch_bounds__(NTHREADS)
apply_kernel(const float* __restrict__ sr, const float* __restrict__ si,
             const float* __restrict__ rabi, float* __restrict__ out)
{
    extern __shared__ float4 smem[];
    float4* smr = smem;            // [GROUPS]
    float4* smi = smem + GROUPS;   // [GROUPS]

    const unsigned chunkG = blockIdx.x * GROUPS;   // global float4-group base
    const float4* grp = (const float4*)sr;
    const float4* gip = (const float4*)si;

    for (int g = threadIdx.x; g < GROUPS; g += NTHREADS) {
        smr[g] = grp[chunkG + g];
        smi[g] = gip[chunkG + g];
    }
    const float c = 0.5f * __ldg(rabi);
    __syncthreads();

#pragma unroll 1
    for (int k = 0; k < GPT; k++) {
        const int G = threadIdx.x + k * NTHREADS;
        float4 vr = smr[G];
        float4 vi = smi[G];

        // m=0 : e^1 swaps (x<->y, z<->w)
        float4 ar = make_float4(vr.y, vr.x, vr.w, vr.z);
        float4 ai = make_float4(vi.y, vi.x, vi.w, vi.z);
        // m=1 : e^2 swaps (x<->z, y<->w)
        ar.x += vr.z; ar.y += vr.w; ar.z += vr.x; ar.w += vr.y;
        ai.x += vi.z; ai.y += vi.w; ai.z += vi.x; ai.w += vi.y;

        // m=2..12 : smem group neighbors (bit t = m-2 of group index)
#pragma unroll
        for (int t = 0; t < 11; t++) {
            int Gn = G ^ (1 << t);
            float4 nr = smr[Gn];
            float4 ni = smi[Gn];
            ar.x += nr.x; ar.y += nr.y; ar.z += nr.z; ar.w += nr.w;
            ai.x += ni.x; ai.y += ni.y; ai.z += ni.z; ai.w += ni.w;
        }

        // m=13..21 : global neighbor chunks (bit t = m-2 of global group idx)
        const unsigned gG = chunkG + G;
#pragma unroll
        for (int t = 11; t < 20; t++) {
            unsigned Gg = gG ^ (1u << t);
            float4 nr = __ldg(&grp[Gg]);
            float4 ni = __ldg(&gip[Gg]);
            ar.x += nr.x; ar.y += nr.y; ar.z += nr.z; ar.w += nr.w;
            ai.x += ni.x; ai.y += ni.y; ai.z += ni.z; ai.w += ni.w;
        }

        float4 dg = ((const float4*)g_diag)[gG];
        float4 outr, outi;
        outr.x = fmaf(dg.x, vr.x, c * ar.x);
        outr.y = fmaf(dg.y, vr.y, c * ar.y);
        outr.z = fmaf(dg.z, vr.z, c * ar.z);
        outr.w = fmaf(dg.w, vr.w, c * ar.w);
        outi.x = fmaf(dg.x, vi.x, c * ai.x);
        outi.y = fmaf(dg.y, vi.y, c * ai.y);
        outi.z = fmaf(dg.z, vi.z, c * ai.z);
        outi.w = fmaf(dg.w, vi.w, c * ai.w);

        ((float4*)out)[gG]              = outr;
        ((float4*)(out + DIM))[gG]      = outi;
    }
}

// ---------------------------------------------------------------------------
// Launch: tables -> diag fill -> apply. All graph-capturable (kernels only).
// ---------------------------------------------------------------------------
extern "C" void kernel_launch(void* const* d_in, const int* in_sizes, int n_in,
                              void* d_out, int out_size)
{
    const float* sr     = (const float*)d_in[0];
    const float* si     = (const float*)d_in[1];
    const float* rabi   = (const float*)d_in[2];
    const float* detune = (const float*)d_in[3];
    const float* U      = (const float*)d_in[4];
    float* out = (float*)d_out;

    cudaFuncSetAttribute(apply_kernel,
                         cudaFuncAttributeMaxDynamicSharedMemorySize,
                         SMEM_BYTES);

    tables_kernel<<<2, 1024>>>(U, detune);
    diag_kernel<<<(DIM / 4) / 256, 256>>>();
    apply_kernel<<<NBLOCKS, NTHREADS, SMEM_BYTES>>>(sr, si, rabi, out);
}

// round 3
// speedup vs baseline: 1.0316x; 1.0316x over previous
#include <cuda_runtime.h>

#define NQ       22
#define DIM      (1u << NQ)        // 4194304
#define BLOG     13
#define CHUNK    (1u << BLOG)      // 8192 elements per CTA (in smem)
#define NTHREADS 512
#define GROUPS   (CHUNK >> 2)      // 2048 float4 groups per chunk
#define GPT      (GROUPS / NTHREADS) // 4 float4 groups per thread
#define NBLOCKS  (DIM / CHUNK)     // 512
#define SMEM_BYTES (2 * GROUPS * 16) // 64 KB

// Scratch (device globals, no allocation)
__device__ float g_diag[DIM];
__device__ float g_dLo[2048];
__device__ float g_dHi[2048];
__device__ float g_R[11][2048];

// ---------------------------------------------------------------------------
// Kernel A: tiny split tables for the diagonal.
//   LSB bit positions p>q carry coefficient M[p][q] = U[21-p][21-q]
//   dLo[lo]  : one-body + pairwise among bits 0..10
//   dHi[hi]  : one-body + pairwise among bits 11..21 (hi bit h -> global 11+h)
//   R[h][lo] : cross terms, sum over set q in lo of U[10-h][21-q]
// ---------------------------------------------------------------------------
__global__ void tables_kernel(const float* __restrict__ U,
                              const float* __restrict__ detune)
{
    int t = blockIdx.x * blockDim.x + threadIdx.x;
    if (t >= 2048) return;
    float det = detune[0];

    float dlo = 0.f;
    for (int p = 0; p < 11; p++) {
        if ((t >> p) & 1) {
            dlo -= det;
            for (int q = 0; q < p; q++)
                if ((t >> q) & 1) dlo += U[(21 - p) * NQ + (21 - q)];
        }
    }
    g_dLo[t] = dlo;

    float dhi = 0.f;
    for (int h = 0; h < 11; h++) {
        if ((t >> h) & 1) {
            dhi -= det;
            for (int h2 = 0; h2 < h; h2++)
                if ((t >> h2) & 1) dhi += U[(10 - h) * NQ + (10 - h2)];
        }
    }
    g_dHi[t] = dhi;

    for (int h = 0; h < 11; h++) {
        float r = 0.f;
        for (int q = 0; q < 11; q++)
            if ((t >> q) & 1) r += U[(10 - h) * NQ + (21 - q)];
        g_R[h][t] = r;
    }
}

// ---------------------------------------------------------------------------
// Kernel B: fill full diagonal array (4M floats) from the split tables.
//   diag[b] = dLo[b & 2047] + dHi[b >> 11] + sum_{h set in hi} R[h][b & 2047]
// Vectorized float4 over lo (tables L1/L2 resident). Branches warp-uniform.
// ---------------------------------------------------------------------------
__global__ void diag_kernel()
{
    unsigned g  = blockIdx.x * blockDim.x + threadIdx.x;  // float4 group id
    unsigned b  = g << 2;
    unsigned lo = b & 2047u;
    unsigned hi = b >> 11;

    float4 d = *(const float4*)&g_dLo[lo];
    float dhi = g_dHi[hi];
    d.x += dhi; d.y += dhi; d.z += dhi; d.w += dhi;
#pragma unroll
    for (int h = 0; h < 11; h++) {
        if ((hi >> h) & 1) {
            float4 r = *(const float4*)&g_R[h][lo];
            d.x += r.x; d.y += r.y; d.z += r.z; d.w += r.w;
        }
    }
    ((float4*)g_diag)[g] = d;
}

// ---------------------------------------------------------------------------
// Kernel C: main apply.
//   out = (rabi/2) * sum over 22 single-bit-flip neighbors + diag * psi
//   bits 0..1   : inside the float4 (register swaps)
//   bits 2..12  : group-XOR inside the 8K-element smem tile (LDS.128)
//   bits 13..21 : coalesced global float4 loads of 9 neighbor chunks
// ---------------------------------------------------------------------------
__global__ void __launch_bounds__(NTHREADS)
apply_kernel(const float* __restrict__ sr, const float* __restrict__ si,
             const float* __restrict__ rabi, float* __restrict__ out)
{
    extern __shared__ float4 smem[];
    float4* smr = smem;            // [GROUPS]
    float4* smi = smem + GROUPS;   // [GROUPS]

    const unsigned chunkG = blockIdx.x * GROUPS;   // global float4-group base
    const float4* grp = (const float4*)sr;
    const float4* gip = (const float4*)si;

    for (int g = threadIdx.x; g < GROUPS; g += NTHREADS) {
        smr[g] = grp[chunkG + g];
        smi[g] = gip[chunkG + g];
    }
    const float c = 0.5f * __ldg(rabi);
    __syncthreads();

#pragma unroll 1
    for (int k = 0; k < GPT; k++) {
        const int G = threadIdx.x + k * NTHREADS;
        float4 vr = smr[G];
        float4 vi = smi[G];

        // m=0 : e^1 swaps (x<->y, z<->w)
        float4 ar = make_float4(vr.y, vr.x, vr.w, vr.z);
        float4 ai = make_float4(vi.y, vi.x, vi.w, vi.z);
        // m=1 : e^2 swaps (x<->z, y<->w)
        ar.x += vr.z; ar.y += vr.w; ar.z += vr.x; ar.w += vr.y;
        ai.x += vi.z; ai.y += vi.w; ai.z += vi.x; ai.w += vi.y;

        // m=2..12 : smem group neighbors (bit t = m-2 of group index)
#pragma unroll
        for (int t = 0; t < 11; t++) {
            int Gn = G ^ (1 << t);
            float4 nr = smr[Gn];
            float4 ni = smi[Gn];
            ar.x += nr.x; ar.y += nr.y; ar.z += nr.z; ar.w += nr.w;
            ai.x += ni.x; ai.y += ni.y; ai.z += ni.z; ai.w += ni.w;
        }

        // m=13..21 : global neighbor chunks (bit t = m-2 of global group idx)
        const unsigned gG = chunkG + G;
#pragma unroll
        for (int t = 11; t < 20; t++) {
            unsigned Gg = gG ^ (1u << t);
            float4 nr = __ldg(&grp[Gg]);
            float4 ni = __ldg(&gip[Gg]);
            ar.x += nr.x; ar.y += nr.y; ar.z += nr.z; ar.w += nr.w;
            ai.x += ni.x; ai.y += ni.y; ai.z += ni.z; ai.w += ni.w;
        }

        float4 dg = ((const float4*)g_diag)[gG];
        float4 outr, outi;
        outr.x = fmaf(dg.x, vr.x, c * ar.x);
        outr.y = fmaf(dg.y, vr.y, c * ar.y);
        outr.z = fmaf(dg.z, vr.z, c * ar.z);
        outr.w = fmaf(dg.w, vr.w, c * ar.w);
        outi.x = fmaf(dg.x, vi.x, c * ai.x);
        outi.y = fmaf(dg.y, vi.y, c * ai.y);
        outi.z = fmaf(dg.z, vi.z, c * ai.z);
        outi.w = fmaf(dg.w, vi.w, c * ai.w);

        ((float4*)out)[gG]              = outr;
        ((float4*)(out + DIM))[gG]      = outi;
    }
}

// ---------------------------------------------------------------------------
// Launch: tables -> diag fill -> apply. All graph-capturable (kernels only).
// ---------------------------------------------------------------------------
extern "C" void kernel_launch(void* const* d_in, const int* in_sizes, int n_in,
                              void* d_out, int out_size)
{
    const float* sr     = (const float*)d_in[0];
    const float* si     = (const float*)d_in[1];
    const float* rabi   = (const float*)d_in[2];
    const float* detune = (const float*)d_in[3];
    const float* U      = (const float*)d_in[4];
    float* out = (float*)d_out;

    cudaFuncSetAttribute(apply_kernel,
                         cudaFuncAttributeMaxDynamicSharedMemorySize,
                         SMEM_BYTES);

    tables_kernel<<<2, 1024>>>(U, detune);
    diag_kernel<<<(DIM / 4) / 256, 256>>>();
    apply_kernel<<<NBLOCKS, NTHREADS, SMEM_BYTES>>>(sr, si, rabi, out);
}

// round 4
// speedup vs baseline: 1.0322x; 1.0006x over previous
#include <cuda_runtime.h>

#define NQ   22
#define DIM  (1u << NQ)     // 4194304 elements per component

// ---- tiny diagonal split tables (device globals, no allocation) ----
__device__ float g_dLo[2048];
__device__ float g_dHi[2048];
__device__ float g_R[11][2048];

__device__ __forceinline__ void add4(float4& a, const float4 b) {
    a.x += b.x; a.y += b.y; a.z += b.z; a.w += b.w;
}

// ---------------------------------------------------------------------------
// Kernel A: split tables for the diagonal.
//   diag[b] = dLo[b&2047] + dHi[b>>11] + sum_{h set in (b>>11)} R[h][b&2047]
//   LSB bit position p carries qubit row (21-p) of U; pair (p>q) -> U[21-p][21-q].
// ---------------------------------------------------------------------------
__global__ void tables_kernel(const float* __restrict__ U,
                              const float* __restrict__ detune)
{
    int t = blockIdx.x * blockDim.x + threadIdx.x;   // 0..2047
    if (t >= 2048) return;
    float det = detune[0];

    float dlo = 0.f;
    for (int p = 0; p < 11; p++) {
        if ((t >> p) & 1) {
            dlo -= det;
            for (int q = 0; q < p; q++)
                if ((t >> q) & 1) dlo += U[(21 - p) * NQ + (21 - q)];
        }
    }
    g_dLo[t] = dlo;

    float dhi = 0.f;
    for (int h = 0; h < 11; h++) {
        if ((t >> h) & 1) {
            dhi -= det;
            for (int h2 = 0; h2 < h; h2++)
                if ((t >> h2) & 1) dhi += U[(10 - h) * NQ + (10 - h2)];
        }
    }
    g_dHi[t] = dhi;

    for (int h = 0; h < 11; h++) {
        float r = 0.f;
        for (int q = 0; q < 11; q++)
            if ((t >> q) & 1) r += U[(10 - h) * NQ + (21 - q)];
        g_R[h][t] = r;
    }
}

// ---------------------------------------------------------------------------
// Pass A: low bits 0..12 (13 X-neighbors) + diagonal, fused.
//   8192-element contiguous smem tile per CTA (2048 float4 groups x {r,i}).
//   bits 0..1  : in-float4 register swaps
//   bits 2..10 : 9 smem XOR neighbors on the group index
//   bits 11..12: register exchange across the thread's own k-groups
//                (G = tid + k*512  ->  G bits 9..10 == k)
//   writes out = diag*psi + c*acc_low
// ---------------------------------------------------------------------------
__global__ void __launch_bounds__(512)
passA_kernel(const float* __restrict__ sr, const float* __restrict__ si,
             const float* __restrict__ rabi, float* __restrict__ out)
{
    extern __shared__ float4 smem[];
    float4* smr = smem;          // [2048]
    float4* smi = smem + 2048;   // [2048]

    const unsigned chunkG = blockIdx.x * 2048u;      // global float4-group base
    const float4* grp = (const float4*)sr;
    const float4* gip = (const float4*)si;
    const int tid = threadIdx.x;

    float4 vr[4], vi[4];
#pragma unroll
    for (int k = 0; k < 4; k++) {
        const int G = tid + k * 512;
        vr[k] = grp[chunkG + G];
        vi[k] = gip[chunkG + G];
        smr[G] = vr[k];
        smi[G] = vi[k];
    }
    const float c = 0.5f * __ldg(rabi);
    __syncthreads();

    float4* outr4 = (float4*)out;
    float4* outi4 = (float4*)(out + DIM);

#pragma unroll
    for (int k = 0; k < 4; k++) {
        const int G = tid + k * 512;
        const float4 r0 = vr[k], i0 = vi[k];

        // element bit 0: swap within pairs
        float4 ar = make_float4(r0.y, r0.x, r0.w, r0.z);
        float4 ai = make_float4(i0.y, i0.x, i0.w, i0.z);
        // element bit 1: swap halves
        ar.x += r0.z; ar.y += r0.w; ar.z += r0.x; ar.w += r0.y;
        ai.x += i0.z; ai.y += i0.w; ai.z += i0.x; ai.w += i0.y;

        // element bits 11,12 -> group bits 9,10 -> thread's own k^1, k^2
        add4(ar, vr[k ^ 1]); add4(ar, vr[k ^ 2]);
        add4(ai, vi[k ^ 1]); add4(ai, vi[k ^ 2]);

        // element bits 2..10 -> group bits 0..8 via smem
#pragma unroll
        for (int t = 0; t < 9; t++) {
            const int Gn = G ^ (1 << t);
            add4(ar, smr[Gn]);
            add4(ai, smi[Gn]);
        }

        // diagonal from split tables (hi is uniform over the 512 threads of one k)
        const unsigned gG = chunkG + G;
        const unsigned lo = (G << 2) & 2047u;
        const unsigned hi = gG >> 9;
        float4 d = *(const float4*)&g_dLo[lo];
        const float dh = g_dHi[hi];
        d.x += dh; d.y += dh; d.z += dh; d.w += dh;
#pragma unroll
        for (int h = 0; h < 11; h++) {
            if ((hi >> h) & 1) {
                const float4 rr = *(const float4*)&g_R[h][lo];
                add4(d, rr);
            }
        }

        float4 o;
        o.x = fmaf(d.x, r0.x, c * ar.x);
        o.y = fmaf(d.y, r0.y, c * ar.y);
        o.z = fmaf(d.z, r0.z, c * ar.z);
        o.w = fmaf(d.w, r0.w, c * ar.w);
        outr4[gG] = o;
        float4 p;
        p.x = fmaf(d.x, i0.x, c * ai.x);
        p.y = fmaf(d.y, i0.y, c * ai.y);
        p.z = fmaf(d.z, i0.z, c * ai.z);
        p.w = fmaf(d.w, i0.w, c * ai.w);
        outi4[gG] = p;
    }
}

// ---------------------------------------------------------------------------
// Pass B: high bits 13..21 (9 X-neighbors), retiled.
//   Tile = 512 high-combinations (bits 13..21) x 32 consecutive elements
//   (bits 0..4); CTA fixes mid = bits 5..12 (256 CTAs). 128KB smem.
//   smem idx = h*8 + jg  (jg = float4 within the 32-element row).
//   All 9 neighbors are XORs on h -> idx ^ (8<<t). RMW: out += c*acc_high.
// ---------------------------------------------------------------------------
__global__ void __launch_bounds__(1024)
passB_kernel(const float* __restrict__ sr, const float* __restrict__ si,
             const float* __restrict__ rabi, float* __restrict__ out)
{
    extern __shared__ float4 smem[];
    float4* smr = smem;          // [4096]
    float4* smi = smem + 4096;   // [4096]

    const unsigned mid = blockIdx.x;                 // element bits 5..12
    const float4* grp = (const float4*)sr;
    const float4* gip = (const float4*)si;
    const int tid = threadIdx.x;

#pragma unroll
    for (int k = 0; k < 4; k++) {
        const int idx = tid + k * 1024;
        const unsigned gG = (unsigned)(idx >> 3) * 2048u + mid * 8u + (idx & 7);
        smr[idx] = grp[gG];
        smi[idx] = gip[gG];
    }
    const float c = 0.5f * __ldg(rabi);
    __syncthreads();

    float4* outr4 = (float4*)out;
    float4* outi4 = (float4*)(out + DIM);

#pragma unroll
    for (int k = 0; k < 4; k++) {
        const int idx = tid + k * 1024;
        float4 ar = make_float4(0.f, 0.f, 0.f, 0.f);
        float4 ai = make_float4(0.f, 0.f, 0.f, 0.f);
#pragma unroll
        for (int t = 0; t < 9; t++) {
            const int n = idx ^ (8 << t);            // flip h bit t -> elem bit 13+t
            add4(ar, smr[n]);
            add4(ai, smi[n]);
        }
        const unsigned gG = (unsigned)(idx >> 3) * 2048u + mid * 8u + (idx & 7);
        float4 o = outr4[gG];
        o.x = fmaf(c, ar.x, o.x);
        o.y = fmaf(c, ar.y, o.y);
        o.z = fmaf(c, ar.z, o.z);
        o.w = fmaf(c, ar.w, o.w);
        outr4[gG] = o;
        float4 p = outi4[gG];
        p.x = fmaf(c, ai.x, p.x);
        p.y = fmaf(c, ai.y, p.y);
        p.z = fmaf(c, ai.z, p.z);
        p.w = fmaf(c, ai.w, p.w);
        outi4[gG] = p;
    }
}

// ---------------------------------------------------------------------------
// Launch: tables -> passA (low + diag, writes out) -> passB (high, RMW out).
// ---------------------------------------------------------------------------
extern "C" void kernel_launch(void* const* d_in, const int* in_sizes, int n_in,
                              void* d_out, int out_size)
{
    const float* sr     = (const float*)d_in[0];
    const float* si     = (const float*)d_in[1];
    const float* rabi   = (const float*)d_in[2];
    const float* detune = (const float*)d_in[3];
    const float* U      = (const float*)d_in[4];
    float* out = (float*)d_out;

    cudaFuncSetAttribute(passA_kernel,
                         cudaFuncAttributeMaxDynamicSharedMemorySize, 65536);
    cudaFuncSetAttribute(passB_kernel,
                         cudaFuncAttributeMaxDynamicSharedMemorySize, 131072);

    tables_kernel<<<32, 64>>>(U, detune);
    passA_kernel<<<DIM / 8192, 512, 65536>>>(sr, si, rabi, out);
    passB_kernel<<<256, 1024, 131072>>>(sr, si, rabi, out);
}